// round 2
// baseline (speedup 1.0000x reference)
#include <cuda_runtime.h>
#include <math.h>

// Problem constants: B=8, C=512, H=W=32 (HW=1024), 8 heads x 64 dim, 32 groups.
// Activations are kept in [channel][b*1024+hw] layout (NCOL = 8*1024 = 8192)
// so both 1x1 convs become single large GEMMs.

#define NCOL 8192

// Scratch (allocation-free rule: __device__ globals)
__device__ float g_xnt [512  * NCOL];   // normalized input, [c][b*HW+hw]
__device__ float g_qkv [1536 * NCOL];   // qkv, row o = head*192 + {q:0..63, k:64..127, v:128..191}
__device__ float g_attn[512  * NCOL];   // attention output, row c = head*64 + d

// ---------------------------------------------------------------------------
// GroupNorm: one block per (b, group). group = 16 ch x 1024 px = 16384 floats.
// Values kept in registers (single gmem read), output written transposed.
// ---------------------------------------------------------------------------
__global__ __launch_bounds__(256) void gn_kernel(const float* __restrict__ x,
                                                 const float* __restrict__ gamma,
                                                 const float* __restrict__ beta)
{
    int b = blockIdx.x >> 5;
    int g = blockIdx.x & 31;
    const float4* xg = (const float4*)(x + ((b * 512 + g * 16) << 10));
    int tid = threadIdx.x;

    float4 v[16];
    float s = 0.f, ss = 0.f;
#pragma unroll
    for (int i = 0; i < 16; i++) {
        float4 t = xg[i * 256 + tid];
        v[i] = t;
        s  += t.x + t.y + t.z + t.w;
        ss += t.x * t.x + t.y * t.y + t.z * t.z + t.w * t.w;
    }
#pragma unroll
    for (int off = 16; off; off >>= 1) {
        s  += __shfl_xor_sync(0xffffffffu, s,  off);
        ss += __shfl_xor_sync(0xffffffffu, ss, off);
    }
    __shared__ float red[8][2];
    __shared__ float stats[2];
    int warp = tid >> 5, lane = tid & 31;
    if (lane == 0) { red[warp][0] = s; red[warp][1] = ss; }
    __syncthreads();
    if (tid == 0) {
        float S = 0.f, SS = 0.f;
#pragma unroll
        for (int w = 0; w < 8; w++) { S += red[w][0]; SS += red[w][1]; }
        float mean = S * (1.f / 16384.f);
        float var  = SS * (1.f / 16384.f) - mean * mean;
        stats[0] = mean;
        stats[1] = rsqrtf(var + 1e-5f);
    }
    __syncthreads();
    float mean = stats[0], rstd = stats[1];

    float4* xnt4 = (float4*)g_xnt;
#pragma unroll
    for (int i = 0; i < 16; i++) {
        int idx4 = i * 256 + tid;       // float4 index inside the group
        int cl   = idx4 >> 8;           // local channel 0..15 (256 float4 per channel)
        int hw4  = idx4 & 255;
        int c    = g * 16 + cl;
        float ga = gamma[c] * rstd;
        float bb = beta[c] - mean * ga;
        float4 t = v[i], o;
        o.x = t.x * ga + bb; o.y = t.y * ga + bb;
        o.z = t.z * ga + bb; o.w = t.w * ga + bb;
        // g_xnt[c][b*1024 + hw]  -> float4 index c*2048 + b*256 + hw4
        xnt4[c * 2048 + b * 256 + hw4] = o;
    }
}

// ---------------------------------------------------------------------------
// SGEMM: C = A[M,K] @ B[K,N] (+bias per row).
// 128x128 block tile, BK=8, 256 threads, 8x8 per thread (split 4+4 fragments
// so float4 smem reads are conflict-free). Next K-tile gmem loads are
// prefetched into registers before the compute phase (hides LDG latency).
// MODE 0: C[r*N+n] = acc + bias[r]           (qkv)
// MODE 1: out[(b*512+r)*1024+hw] = acc + bias[r] + resid[...]  (proj+residual)
// ---------------------------------------------------------------------------
template <int MODE>
__global__ __launch_bounds__(256) void sgemm_kernel(
        const float* __restrict__ A, const float* __restrict__ Bm,
        const float* __restrict__ bias, const float* __restrict__ resid,
        float* __restrict__ C, int M, int N, int K)
{
    __shared__ float As[8][128];
    __shared__ float Bs[8][128];

    int tid = threadIdx.x;
    int m0 = blockIdx.y << 7, n0 = blockIdx.x << 7;
    int tx = tid & 15, ty = tid >> 4;

    int arow = tid >> 1,      acol = (tid & 1)  << 2;
    int brow = tid >> 5,      bcol = (tid & 31) << 2;
    const float* Aptr = A  + (m0 + arow) * K + acol;
    const float* Bptr = Bm + brow * N + n0 + bcol;

    float acc[8][8];
#pragma unroll
    for (int i = 0; i < 8; i++)
#pragma unroll
        for (int j = 0; j < 8; j++) acc[i][j] = 0.f;

    float4 a4 = *(const float4*)(Aptr);
    float4 b4 = *(const float4*)(Bptr);

    for (int k0 = 0; k0 < K; k0 += 8) {
        As[acol + 0][arow] = a4.x; As[acol + 1][arow] = a4.y;
        As[acol + 2][arow] = a4.z; As[acol + 3][arow] = a4.w;
        *(float4*)&Bs[brow][bcol] = b4;
        __syncthreads();

        if (k0 + 8 < K) {   // prefetch next tile while computing this one
            a4 = *(const float4*)(Aptr + k0 + 8);
            b4 = *(const float4*)(Bptr + (k0 + 8) * N);
        }

#pragma unroll
        for (int k = 0; k < 8; k++) {
            float ar[8], br[8];
            *(float4*)&ar[0] = *(const float4*)&As[k][ty * 4];
            *(float4*)&ar[4] = *(const float4*)&As[k][64 + ty * 4];
            *(float4*)&br[0] = *(const float4*)&Bs[k][tx * 4];
            *(float4*)&br[4] = *(const float4*)&Bs[k][64 + tx * 4];
#pragma unroll
            for (int i = 0; i < 8; i++)
#pragma unroll
                for (int j = 0; j < 8; j++)
                    acc[i][j] = fmaf(ar[i], br[j], acc[i][j]);
        }
        __syncthreads();
    }

#pragma unroll
    for (int hi = 0; hi < 2; hi++)
#pragma unroll
    for (int ii = 0; ii < 4; ii++) {
        int r = m0 + hi * 64 + ty * 4 + ii;
        float bv = bias[r];
#pragma unroll
        for (int hj = 0; hj < 2; hj++) {
            int cb = n0 + hj * 64 + tx * 4;
            float4 o;
            o.x = acc[hi * 4 + ii][hj * 4 + 0] + bv;
            o.y = acc[hi * 4 + ii][hj * 4 + 1] + bv;
            o.z = acc[hi * 4 + ii][hj * 4 + 2] + bv;
            o.w = acc[hi * 4 + ii][hj * 4 + 3] + bv;
            if (MODE == 0) {
                *(float4*)&C[r * N + cb] = o;
            } else {
                int bidx = cb >> 10;
                int hw   = cb & 1023;
                int oidx = ((bidx << 9) + r) * 1024 + hw;  // x / out layout [b][c][hw]
                float4 rv = *(const float4*)&resid[oidx];
                o.x += rv.x; o.y += rv.y; o.z += rv.z; o.w += rv.w;
                *(float4*)&C[oidx] = o;
            }
        }
    }
}

// ---------------------------------------------------------------------------
// Flash attention, fp32. Grid: (32 q-tiles, 64 b*head). 128 threads.
// BQ=32 queries/block, BKV=64 keys/tile, d=64.
// Smem: Qs[64d][32q], Ks[64d][64j] (aliased as P[32][64] after scores),
//       Vt[64j][64d + 4 pad] (transposed for float4 reads).
// ---------------------------------------------------------------------------
__global__ __launch_bounds__(128) void attn_kernel()
{
    __shared__ float Qs[64][32];
    __shared__ float Ks[64][64];     // reused as P tile (first 32*64 floats)
    __shared__ float Vt[64][68];
    __shared__ float m_s[32], l_s[32], alpha_s[32];

    int tid  = threadIdx.x;
    int bh   = blockIdx.y;
    int b    = bh >> 3, head = bh & 7;
    int q0   = blockIdx.x << 5;

    const float* qp = g_qkv + (head * 192      ) * NCOL + b * 1024 + q0;
    const float* kp = g_qkv + (head * 192 +  64) * NCOL + b * 1024;
    const float* vp = g_qkv + (head * 192 + 128) * NCOL + b * 1024;

    // Q tile: 64 x 32 floats = 512 float4
#pragma unroll
    for (int rep = 0; rep < 4; rep++) {
        int lin = rep * 128 + tid;
        int d = lin >> 3, i4 = lin & 7;
        *(float4*)&Qs[d][i4 << 2] = *(const float4*)(qp + d * NCOL + (i4 << 2));
    }
    if (tid < 32) { m_s[tid] = -1e30f; l_s[tid] = 0.f; }

    int tx = tid & 15, ty = tid >> 4;   // thread computes rows ty*4.., cols tx*4..
    float acc[4][4];
#pragma unroll
    for (int a = 0; a < 4; a++)
#pragma unroll
        for (int c = 0; c < 4; c++) acc[a][c] = 0.f;

    float* Ss = &Ks[0][0];   // alias: P[r][j] = Ss[r*64+j]
    __syncthreads();

    for (int kt = 0; kt < 16; kt++) {
        int j0 = kt << 6;
        // K tile: 64 x 64 floats = 1024 float4
#pragma unroll
        for (int rep = 0; rep < 8; rep++) {
            int lin = rep * 128 + tid;
            int d = lin >> 4, j4 = lin & 15;
            *(float4*)&Ks[d][j4 << 2] = *(const float4*)(kp + d * NCOL + j0 + (j4 << 2));
        }
        // V tile (transposed into Vt[j][d])
#pragma unroll
        for (int rep = 0; rep < 8; rep++) {
            int lin = rep * 128 + tid;
            int d = lin >> 4, j4 = lin & 15;
            float4 vv = *(const float4*)(vp + d * NCOL + j0 + (j4 << 2));
            Vt[(j4 << 2) + 0][d] = vv.x;
            Vt[(j4 << 2) + 1][d] = vv.y;
            Vt[(j4 << 2) + 2][d] = vv.z;
            Vt[(j4 << 2) + 3][d] = vv.w;
        }
        __syncthreads();

        // S = Q^T K  (4x4 per thread)
        float s[4][4];
#pragma unroll
        for (int a = 0; a < 4; a++)
#pragma unroll
            for (int c = 0; c < 4; c++) s[a][c] = 0.f;
#pragma unroll 16
        for (int d = 0; d < 64; d++) {
            float4 qa = *(const float4*)&Qs[d][ty << 2];
            float4 kb = *(const float4*)&Ks[d][tx << 2];
            s[0][0] = fmaf(qa.x, kb.x, s[0][0]); s[0][1] = fmaf(qa.x, kb.y, s[0][1]);
            s[0][2] = fmaf(qa.x, kb.z, s[0][2]); s[0][3] = fmaf(qa.x, kb.w, s[0][3]);
            s[1][0] = fmaf(qa.y, kb.x, s[1][0]); s[1][1] = fmaf(qa.y, kb.y, s[1][1]);
            s[1][2] = fmaf(qa.y, kb.z, s[1][2]); s[1][3] = fmaf(qa.y, kb.w, s[1][3]);
            s[2][0] = fmaf(qa.z, kb.x, s[2][0]); s[2][1] = fmaf(qa.z, kb.y, s[2][1]);
            s[2][2] = fmaf(qa.z, kb.z, s[2][2]); s[2][3] = fmaf(qa.z, kb.w, s[2][3]);
            s[3][0] = fmaf(qa.w, kb.x, s[3][0]); s[3][1] = fmaf(qa.w, kb.y, s[3][1]);
            s[3][2] = fmaf(qa.w, kb.z, s[3][2]); s[3][3] = fmaf(qa.w, kb.w, s[3][3]);
        }
        __syncthreads();   // everyone done reading Ks -> safe to overwrite as P

        // store scaled scores into P tile
#pragma unroll
        for (int ii = 0; ii < 4; ii++) {
            float4 p;
            p.x = s[ii][0] * 0.125f; p.y = s[ii][1] * 0.125f;
            p.z = s[ii][2] * 0.125f; p.w = s[ii][3] * 0.125f;
            *(float4*)&Ss[((ty << 2) + ii) * 64 + (tx << 2)] = p;
        }
        __syncthreads();

        // online softmax: 4 threads per row (same warp), 16 elems each
        {
            int r = tid >> 2, part = tid & 3;
            float* row = &Ss[r * 64 + part * 16];
            float mx = -1e30f;
#pragma unroll
            for (int t = 0; t < 16; t++) mx = fmaxf(mx, row[t]);
            mx = fmaxf(mx, __shfl_xor_sync(0xffffffffu, mx, 1));
            mx = fmaxf(mx, __shfl_xor_sync(0xffffffffu, mx, 2));
            float m_old = m_s[r];
            float m_new = fmaxf(m_old, mx);
            float sum = 0.f;
#pragma unroll
            for (int t = 0; t < 16; t++) {
                float p = __expf(row[t] - m_new);
                row[t] = p;
                sum += p;
            }
            sum += __shfl_xor_sync(0xffffffffu, sum, 1);
            sum += __shfl_xor_sync(0xffffffffu, sum, 2);
            if (part == 0) {
                float al = __expf(m_old - m_new);
                m_s[r] = m_new;
                l_s[r] = l_s[r] * al + sum;
                alpha_s[r] = al;
            }
        }
        __syncthreads();

        // O = O*alpha + P @ V^T
#pragma unroll
        for (int ii = 0; ii < 4; ii++) {
            float al = alpha_s[(ty << 2) + ii];
            acc[ii][0] *= al; acc[ii][1] *= al; acc[ii][2] *= al; acc[ii][3] *= al;
        }
#pragma unroll 8
        for (int j = 0; j < 64; j++) {
            float4 v4 = *(const float4*)&Vt[j][tx << 2];
#pragma unroll
            for (int ii = 0; ii < 4; ii++) {
                float p = Ss[((ty << 2) + ii) * 64 + j];
                acc[ii][0] = fmaf(p, v4.x, acc[ii][0]);
                acc[ii][1] = fmaf(p, v4.y, acc[ii][1]);
                acc[ii][2] = fmaf(p, v4.z, acc[ii][2]);
                acc[ii][3] = fmaf(p, v4.w, acc[ii][3]);
            }
        }
        __syncthreads();  // before next tile overwrites Ks/Vt
    }

    // epilogue: normalize and write [c = head*64+d][b*1024 + q]
    float* outp = g_attn + (head * 64) * NCOL + b * 1024 + q0;
#pragma unroll
    for (int ii = 0; ii < 4; ii++) {
        float inv = 1.f / l_s[(ty << 2) + ii];
#pragma unroll
        for (int dd = 0; dd < 4; dd++)
            outp[((tx << 2) + dd) * NCOL + (ty << 2) + ii] = acc[ii][dd] * inv;
    }
}

// ---------------------------------------------------------------------------
extern "C" void kernel_launch(void* const* d_in, const int* in_sizes, int n_in,
                              void* d_out, int out_size)
{
    const float* x    = (const float*)d_in[0];
    const float* gnw  = (const float*)d_in[1];
    const float* gnb  = (const float*)d_in[2];
    const float* qkvw = (const float*)d_in[3];
    const float* qkvb = (const float*)d_in[4];
    const float* outw = (const float*)d_in[5];
    const float* outb = (const float*)d_in[6];
    float* out = (float*)d_out;

    float *xnt, *qkv, *attn;
    cudaGetSymbolAddress((void**)&xnt,  g_xnt);
    cudaGetSymbolAddress((void**)&qkv,  g_qkv);
    cudaGetSymbolAddress((void**)&attn, g_attn);

    // 1. GroupNorm (writes transposed activations)
    gn_kernel<<<256, 256>>>(x, gnw, gnb);
    // 2. QKV projection: [1536,512] @ [512,8192]
    sgemm_kernel<0><<<dim3(64, 12), 256>>>(qkvw, xnt, qkvb, nullptr, qkv, 1536, NCOL, 512);
    // 3. Flash attention per (b, head)
    attn_kernel<<<dim3(32, 64), 128>>>();
    // 4. Output projection + bias + residual: [512,512] @ [512,8192] -> d_out
    sgemm_kernel<1><<<dim3(64, 4), 256>>>(outw, attn, outb, x, out, 512, NCOL, 512);
}